// round 15
// baseline (speedup 1.0000x reference)
#include <cuda_runtime.h>
#include <math.h>

#define B_   32
#define F_   256
#define T_   4096
#define NPB  (F_ * T_)
#define PADL 256

// blur tile: TF freq rows x TT time cols per block, 5 warps (160 threads).
// Lane l of warp w owns time-column ct = t0 + 26w + l - 3.
// p1 valid all lanes; blurred w valid lanes 2..29; peak2 emitted lanes 3..28
// -> 26 output cols per warp, 5 warps cover 130 >= 128.
#define TF    32
#define TT    128
#define NTHR  160
#define FH    40          // input rows (halo 4): global fr0-4 .. fr0+35
#define FW    137         // input cols in smem: global t0-4 .. t0+132
#define FST   140         // smem row stride
#define SLCAP 2048        // per-block candidate cap
#define CAP   (1 << 18)   // per-batch candidate cap

// Scratch: per-batch candidate lists + min/max keys. (No blurred-field buffer!)
__device__ uint2    g_cand[(size_t)B_ * CAP];
__device__ unsigned g_ccnt[B_];
__device__ unsigned g_mx1[B_], g_mn1[B_], g_mx2[B_], g_mn2[B_];

// Order-preserving float<->uint mapping for atomic min/max.
__device__ __forceinline__ unsigned fkey(float f) {
    unsigned u = __float_as_uint(f);
    return (u & 0x80000000u) ? ~u : (u | 0x80000000u);
}
__device__ __forceinline__ float funkey(unsigned k) {
    unsigned u = (k & 0x80000000u) ? (k & 0x7fffffffu) : ~k;
    return __uint_as_float(u);
}

__global__ void init_k() {
    int i = threadIdx.x;
    if (i < B_) {
        g_mx1[i] = 0u;          g_mn1[i] = 0xFFFFFFFFu;
        g_mx2[i] = 0u;          g_mn2[i] = 0xFFFFFFFFu;
        g_ccnt[i] = 0u;
    }
}

// Stage A: per-batch min/max of the raw input. grid = (64, B_), 256 threads.
__global__ void minmax1_k(const float* __restrict__ in) {
    int b = blockIdx.y;
    const float4* p = (const float4*)(in + (size_t)b * NPB);
    int stride = gridDim.x * blockDim.x;
    int t = blockIdx.x * blockDim.x + threadIdx.x;
    float mx = -INFINITY, mn = INFINITY;
    for (int i = t; i < NPB / 4; i += stride) {
        float4 v = p[i];
        mx = fmaxf(mx, fmaxf(fmaxf(v.x, v.y), fmaxf(v.z, v.w)));
        mn = fminf(mn, fminf(fminf(v.x, v.y), fminf(v.z, v.w)));
    }
#pragma unroll
    for (int o = 16; o > 0; o >>= 1) {
        mx = fmaxf(mx, __shfl_xor_sync(0xffffffffu, mx, o));
        mn = fminf(mn, __shfl_xor_sync(0xffffffffu, mn, o));
    }
    __shared__ float smx[8], smn[8];
    int lane = threadIdx.x & 31, w = threadIdx.x >> 5;
    if (lane == 0) { smx[w] = mx; smn[w] = mn; }
    __syncthreads();
    if (threadIdx.x == 0) {
        for (int i = 1; i < (int)(blockDim.x >> 5); i++) {
            mx = fmaxf(mx, smx[i]); mn = fminf(mn, smn[i]);
        }
        atomicMax(&g_mx1[b], fkey(mx));
        atomicMin(&g_mn1[b], fkey(mn));
    }
}

// Stage B: fully fused peak1 -> normalize -> freq blur -> time blur -> peak2
// candidate emission + blurred-field min/max. Rolling registers, one smem tile.
// grid = (T/TT=32, F/TF=8, B), block = 160 threads (5 warps).
__global__ __launch_bounds__(NTHR)
void blur_k(const float* __restrict__ in, float gw0, float gw1, float gw2) {
    __shared__ float    f_s[FH][FST];
    __shared__ uint2    s_list[SLCAP];
    __shared__ unsigned s_cnt;
    __shared__ unsigned s_gbase;
    __shared__ float    smx[5], smn[5];

    const int b    = blockIdx.z;
    const int fr0  = blockIdx.y * TF;
    const int t0   = blockIdx.x * TT;
    const int tid  = threadIdx.x;
    const int lane = tid & 31;
    const int w    = tid >> 5;
    const float* __restrict__ fin = in + (size_t)b * NPB;

    const bool int_f = (blockIdx.y > 0) && (blockIdx.y < gridDim.y - 1);
    const bool int_t = (blockIdx.x > 0) && (blockIdx.x < gridDim.x - 1);
    const bool topE = (fr0 == 0);
    const bool botE = (fr0 == F_ - TF);

    if (tid == 0) s_cnt = 0;

    // ---- Load input tile (rows fr0-4..fr0+35, cols t0-4..t0+132); -inf outside ----
    if (tid < FW) {
        int ac = t0 - 4 + tid;
        if (int_f && int_t) {
            const float* cp = fin + (size_t)(fr0 - 4) * T_ + ac;
#pragma unroll
            for (int r = 0; r < FH; r++) f_s[r][tid] = cp[(size_t)r * T_];
        } else {
            bool cok = (ac >= 0) && (ac < T_);
#pragma unroll
            for (int r = 0; r < FH; r++) {
                int ar = fr0 - 4 + r;
                float v = -INFINITY;
                if (cok && ar >= 0 && ar < F_) v = fin[(size_t)ar * T_ + ac];
                f_s[r][tid] = v;
            }
        }
    }
    __syncthreads();

    const float mn1  = funkey(g_mn1[b]);
    const float inv1 = 1.0f / (funkey(g_mx1[b]) - mn1);

    const int ci   = 26 * w + lane + 1;           // f_s col of ct
    const int ocol = 26 * w + lane - 3;           // output column rel. t0
    const int gx   = t0 + ocol;                   // global time col of this lane
    const bool out_ok = (lane >= 3) && (lane <= 28) && (ocol < TT);

    float ring[5];
    float w0 = 0.f, w1 = 0.f, w2 = 0.f;
    float bmx = -INFINITY, bmn = INFINITY;

    float fa = f_s[0][ci];
    float tl = f_s[1][ci - 1], tc = f_s[1][ci], tr = f_s[1][ci + 1];

#pragma unroll
    for (int s = 0; s < 38; s++) {                // p1 row pr = s - 3 in [-3, 34]
        float nl = f_s[s + 2][ci - 1], nc = f_s[s + 2][ci], nr = f_s[s + 2][ci + 1];
        bool m = (tc >= fa) && (tc >= nc) && (tc >= tl) && (tc >= tr);
        ring[s % 5] = m ? (tc - mn1) * inv1 : 0.f;

        if (s >= 4) {
            const int r = s - 5;                  // blurred row in [-1, 32]
            float wnew;
            if ((topE && r == -1) || (botE && r == 32)) {
                wnew = -INFINITY;                 // SAME-pad for peak2 freq test
            } else {
                // freq blur from ring (p1 rows r-2..r+2)
                float p0  = ring[(s - 4) % 5];
                float p1v = ring[(s - 3) % 5];
                float p2  = ring[(s - 2) % 5];
                float p3  = ring[(s - 1) % 5];
                float p4  = ring[ s      % 5];
                float tv;
                if (topE && r == 0)
                    tv = fmaf(2.f * gw1, p3, fmaf(2.f * gw0, p4, gw2 * p2));
                else if (topE && r == 1)
                    tv = fmaf(gw1, p1v, fmaf(gw0 + gw2, p2, fmaf(gw1, p3, gw0 * p4)));
                else if (botE && r == 30)
                    tv = fmaf(gw0, p0, fmaf(gw1, p1v, fmaf(gw2 + gw0, p2, gw1 * p3)));
                else if (botE && r == 31)
                    tv = fmaf(2.f * gw0, p0, fmaf(2.f * gw1, p1v, gw2 * p2));
                else {
                    float s0 = p0 + p4, s1 = p1v + p3;
                    tv = fmaf(gw0, s0, fmaf(gw1, s1, gw2 * p2));
                }
                // time blur via shuffles
                float vm1 = __shfl_up_sync(0xffffffffu, tv, 1);
                float vm2 = __shfl_up_sync(0xffffffffu, tv, 2);
                float vp1 = __shfl_down_sync(0xffffffffu, tv, 1);
                float vp2 = __shfl_down_sync(0xffffffffu, tv, 2);
                if (gx == 0)
                    wnew = fmaf(2.f * gw1, vp1, fmaf(2.f * gw0, vp2, gw2 * tv));
                else if (gx == 1)
                    wnew = fmaf(gw1, vm1, fmaf(gw0 + gw2, tv, fmaf(gw1, vp1, gw0 * vp2)));
                else if (gx == T_ - 2)
                    wnew = fmaf(gw0, vm2, fmaf(gw1, vm1, fmaf(gw2 + gw0, tv, gw1 * vp1)));
                else if (gx == T_ - 1)
                    wnew = fmaf(2.f * gw0, vm2, fmaf(2.f * gw1, vm1, gw2 * tv));
                else {
                    float s0 = vm2 + vp2, s1 = vm1 + vp1;
                    wnew = fmaf(gw0, s0, fmaf(gw1, s1, gw2 * tv));
                }
            }
            w2 = wnew;

            if (s >= 6) {
                const int q = s - 6;              // peak2 row in [0, 31]
                // time neighbors of w1 (row q)
                float wl = __shfl_up_sync(0xffffffffu, w1, 1);
                float wr = __shfl_down_sync(0xffffffffu, w1, 1);
                float wl_e = (gx == 0)      ? -INFINITY : wl;
                float wr_e = (gx == T_ - 1) ? -INFINITY : wr;
                bool m2 = (w1 >= w0) && (w1 >= w2) && (w1 >= wl_e) && (w1 >= wr_e);
                bool pred = out_ok && m2 && (w1 > 0.f);
                if (out_ok) { bmx = fmaxf(bmx, w1); bmn = fminf(bmn, w1); }

                unsigned bal = __ballot_sync(0xffffffffu, pred);
                if (bal) {
                    unsigned base = 0;
                    if (lane == 0) base = atomicAdd(&s_cnt, (unsigned)__popc(bal));
                    base = __shfl_sync(0xffffffffu, base, 0);
                    if (pred) {
                        unsigned pos = base + (unsigned)__popc(bal & ((1u << lane) - 1u));
                        if (pos < SLCAP) {
                            s_list[pos].x = (unsigned)((fr0 + q) * T_ + gx);
                            s_list[pos].y = __float_as_uint(w1);
                        }
                    }
                }
            }
            w0 = w1; w1 = w2;
        }
        fa = tc; tl = nl; tc = nc; tr = nr;
    }

    // ---- per-batch min/max of the blurred field ----
#pragma unroll
    for (int o = 16; o > 0; o >>= 1) {
        bmx = fmaxf(bmx, __shfl_xor_sync(0xffffffffu, bmx, o));
        bmn = fminf(bmn, __shfl_xor_sync(0xffffffffu, bmn, o));
    }
    if (lane == 0) { smx[w] = bmx; smn[w] = bmn; }
    __syncthreads();
    if (tid == 0) {
        bmx = smx[0]; bmn = smn[0];
#pragma unroll
        for (int i = 1; i < 5; i++) {
            bmx = fmaxf(bmx, smx[i]); bmn = fminf(bmn, smn[i]);
        }
        atomicMax(&g_mx2[b], fkey(bmx));
        atomicMin(&g_mn2[b], fkey(bmn));
        unsigned cnt = s_cnt; if (cnt > SLCAP) cnt = SLCAP;
        s_cnt = cnt;
        s_gbase = atomicAdd(&g_ccnt[b], cnt);
    }
    __syncthreads();

    // ---- flush block candidate list to the per-batch global list ----
    unsigned cnt = s_cnt, gbase = s_gbase;
    uint2* gc = g_cand + (size_t)b * CAP;
    for (unsigned i = tid; i < cnt; i += NTHR) {
        unsigned p = gbase + i;
        if (p < CAP) gc[p] = s_list[i];
    }
}

// Stage C: per batch, select the first PADL (row-major) candidates with
// val > 0, in order, and write the [3, PADL] output. One block per batch.
__global__ __launch_bounds__(1024)
void final_k(float* __restrict__ out) {
    __shared__ int hist[256];
    __shared__ unsigned long long keys[512];
    __shared__ int s_par[4];   // R, C1, Cb, K
    __shared__ int s_cnt;

    const int b = blockIdx.x;
    const int tid = threadIdx.x;
    unsigned n = g_ccnt[b]; if (n > CAP) n = CAP;
    const float mn2 = funkey(g_mn2[b]);
    const float rng2 = funkey(g_mx2[b]) - mn2;
    const uint2* cand = g_cand + (size_t)b * CAP;
    float* ob = out + b * 3 * PADL;

    if (tid < 3 * PADL) ob[tid] = 0.f;
    if (tid < 256) hist[tid] = 0;
    if (tid == 0) s_cnt = 0;
    __syncthreads();

    // Pass 1: histogram of valid candidates by freq row.
    for (unsigned i = tid; i < n; i += 1024) {
        uint2 c = cand[i];
        if (__uint_as_float(c.y) > mn2) atomicAdd(&hist[c.x >> 12], 1);
    }
    __syncthreads();
    if (tid == 0) {
        int cum = 0, R = 256, C1 = 0;
        for (int r = 0; r < 256; r++) {
            int h = hist[r];
            if (R == 256 && cum + h >= PADL) { R = r; C1 = cum; }
            cum += h;
        }
        if (cum <= PADL) { R = 256; C1 = cum; }   // collect everything
        s_par[0] = R; s_par[1] = C1;
        s_par[3] = (cum < PADL) ? cum : PADL;
    }
    __syncthreads();
    const int R = s_par[0];
    const int K = s_par[3];
    int Cb = 256;

    if (R < 256) {
        // Pass 2: 16-col-bucket histogram within cutoff row R.
        if (tid < 256) hist[tid] = 0;
        __syncthreads();
        for (unsigned i = tid; i < n; i += 1024) {
            uint2 c = cand[i];
            if ((c.x >> 12) == (unsigned)R && __uint_as_float(c.y) > mn2)
                atomicAdd(&hist[(c.x & (T_ - 1)) >> 4], 1);
        }
        __syncthreads();
        if (tid == 0) {
            int cum = s_par[1], CbL = 255;
            for (int bb = 0; bb < 256; bb++) {
                cum += hist[bb];
                if (cum >= PADL) { CbL = bb; break; }
            }
            s_par[2] = CbL;
        }
        __syncthreads();
        Cb = s_par[2];
    }

    // Pass 3: collect candidates below the cutoff (<= 256 + 15 entries).
    for (unsigned i = tid; i < n; i += 1024) {
        uint2 c = cand[i];
        if (__uint_as_float(c.y) > mn2) {
            int row = c.x >> 12;
            bool keep = (row < R) ||
                        (row == R && (int)((c.x & (T_ - 1)) >> 4) <= Cb);
            if (keep) {
                int p = atomicAdd(&s_cnt, 1);
                if (p < 512)
                    keys[p] = ((unsigned long long)c.x << 32) | (unsigned long long)c.y;
            }
        }
    }
    __syncthreads();
    int cnt = s_cnt; if (cnt > 512) cnt = 512;
    for (int i = tid; i < 512; i += 1024)
        if (i >= cnt) keys[i] = 0xFFFFFFFFFFFFFFFFull;
    __syncthreads();

    // Bitonic sort 512 by packed (idx, vbits) key (idx unique).
    for (int k = 2; k <= 512; k <<= 1) {
        for (int j = k >> 1; j > 0; j >>= 1) {
            if (tid < 512) {
                int i2 = tid, ixj = i2 ^ j;
                if (ixj > i2) {
                    bool up = ((i2 & k) == 0);
                    unsigned long long a = keys[i2], c2 = keys[ixj];
                    if ((a > c2) == up) { keys[i2] = c2; keys[ixj] = a; }
                }
            }
            __syncthreads();
        }
    }

    if (tid < K) {
        unsigned long long e = keys[tid];
        unsigned idx = (unsigned)(e >> 32);
        float v = __uint_as_float((unsigned)(e & 0xFFFFFFFFull));
        ob[tid]            = (float)(idx >> 12) * (1.0f / F_);
        ob[PADL + tid]     = (float)(idx & (T_ - 1)) * (1.0f / T_);
        ob[2 * PADL + tid] = __fdiv_rn(v - mn2, rng2);
    }
}

extern "C" void kernel_launch(void* const* d_in, const int* in_sizes, int n_in,
                              void* d_out, int out_size) {
    const float* in = (const float*)d_in[0];
    float* out = (float*)d_out;

    // Gaussian weights, fp32, same formula as the reference.
    float g[5];
    float s = 0.f;
    for (int i = 0; i < 5; i++) {
        float c = (float)(i - 2);
        g[i] = expf(-0.5f * c * c);
    }
    for (int i = 0; i < 5; i++) s += g[i];
    for (int i = 0; i < 5; i++) g[i] = g[i] / s;

    init_k<<<1, 32>>>();
    minmax1_k<<<dim3(64, B_), 256>>>(in);
    blur_k<<<dim3(T_ / TT, F_ / TF, B_), NTHR>>>(in, g[0], g[1], g[2]);
    final_k<<<B_, 1024>>>(out);
}

// round 16
// speedup vs baseline: 1.0029x; 1.0029x over previous
#include <cuda_runtime.h>
#include <math.h>

#define B_   32
#define F_   256
#define T_   4096
#define NPB  (F_ * T_)
#define PADL 256

// blur tile: TF freq rows x TT time cols per block, 5 warps (160 threads).
// Lane l of warp w owns time-column ct = t0 + 26w + l - 3.
// p1 valid all lanes; blurred w valid lanes 2..29; peak2 emitted lanes 3..28
// -> 26 output cols per warp, 5 warps cover 130 >= 128.
#define TF    32
#define TT    128
#define NTHR  160
#define FH    40          // input rows (halo 4): global fr0-4 .. fr0+35
#define FW    137         // input cols in smem: global t0-4 .. t0+132
#define FST   140         // smem row stride
#define SLCAP 2048        // per-block candidate cap
#define CAP   (1 << 18)   // per-batch candidate cap

// Scratch: per-batch candidate lists + min/max keys. (No blurred-field buffer!)
__device__ uint2    g_cand[(size_t)B_ * CAP];
__device__ unsigned g_ccnt[B_];
__device__ unsigned g_mx1[B_], g_mn1[B_], g_mx2[B_], g_mn2[B_];

// Order-preserving float<->uint mapping for atomic min/max.
__device__ __forceinline__ unsigned fkey(float f) {
    unsigned u = __float_as_uint(f);
    return (u & 0x80000000u) ? ~u : (u | 0x80000000u);
}
__device__ __forceinline__ float funkey(unsigned k) {
    unsigned u = (k & 0x80000000u) ? (k & 0x7fffffffu) : ~k;
    return __uint_as_float(u);
}

__global__ void init_k() {
    int i = threadIdx.x;
    if (i < B_) {
        g_mx1[i] = 0u;          g_mn1[i] = 0xFFFFFFFFu;
        g_mx2[i] = 0u;          g_mn2[i] = 0xFFFFFFFFu;
        g_ccnt[i] = 0u;
    }
}

// Stage A: per-batch min/max of the raw input. grid = (64, B_), 256 threads.
__global__ void minmax1_k(const float* __restrict__ in) {
    int b = blockIdx.y;
    const float4* p = (const float4*)(in + (size_t)b * NPB);
    int stride = gridDim.x * blockDim.x;
    int t = blockIdx.x * blockDim.x + threadIdx.x;
    float mx = -INFINITY, mn = INFINITY;
    for (int i = t; i < NPB / 4; i += stride) {
        float4 v = p[i];
        mx = fmaxf(mx, fmaxf(fmaxf(v.x, v.y), fmaxf(v.z, v.w)));
        mn = fminf(mn, fminf(fminf(v.x, v.y), fminf(v.z, v.w)));
    }
#pragma unroll
    for (int o = 16; o > 0; o >>= 1) {
        mx = fmaxf(mx, __shfl_xor_sync(0xffffffffu, mx, o));
        mn = fminf(mn, __shfl_xor_sync(0xffffffffu, mn, o));
    }
    __shared__ float smx[8], smn[8];
    int lane = threadIdx.x & 31, w = threadIdx.x >> 5;
    if (lane == 0) { smx[w] = mx; smn[w] = mn; }
    __syncthreads();
    if (threadIdx.x == 0) {
        for (int i = 1; i < (int)(blockDim.x >> 5); i++) {
            mx = fmaxf(mx, smx[i]); mn = fminf(mn, smn[i]);
        }
        atomicMax(&g_mx1[b], fkey(mx));
        atomicMin(&g_mn1[b], fkey(mn));
    }
}

// Stage B: fully fused peak1 -> normalize -> freq blur -> time blur -> peak2
// candidate emission + blurred-field min/max. Rolling registers, one smem tile.
// grid = (T/TT=32, F/TF=8, B), block = 160 threads (5 warps).
__global__ __launch_bounds__(NTHR)
void blur_k(const float* __restrict__ in, float gw0, float gw1, float gw2) {
    __shared__ float    f_s[FH][FST];
    __shared__ uint2    s_list[SLCAP];
    __shared__ unsigned s_cnt;
    __shared__ unsigned s_gbase;
    __shared__ float    smx[5], smn[5];

    const int b    = blockIdx.z;
    const int fr0  = blockIdx.y * TF;
    const int t0   = blockIdx.x * TT;
    const int tid  = threadIdx.x;
    const int lane = tid & 31;
    const int w    = tid >> 5;
    const float* __restrict__ fin = in + (size_t)b * NPB;

    const bool int_f = (blockIdx.y > 0) && (blockIdx.y < gridDim.y - 1);
    const bool int_t = (blockIdx.x > 0) && (blockIdx.x < gridDim.x - 1);
    const bool topE = (fr0 == 0);
    const bool botE = (fr0 == F_ - TF);

    if (tid == 0) s_cnt = 0;

    // ---- Load input tile (rows fr0-4..fr0+35, cols t0-4..t0+132); -inf outside ----
    if (tid < FW) {
        int ac = t0 - 4 + tid;
        if (int_f && int_t) {
            const float* cp = fin + (size_t)(fr0 - 4) * T_ + ac;
#pragma unroll
            for (int r = 0; r < FH; r++) f_s[r][tid] = cp[(size_t)r * T_];
        } else {
            bool cok = (ac >= 0) && (ac < T_);
#pragma unroll
            for (int r = 0; r < FH; r++) {
                int ar = fr0 - 4 + r;
                float v = -INFINITY;
                if (cok && ar >= 0 && ar < F_) v = fin[(size_t)ar * T_ + ac];
                f_s[r][tid] = v;
            }
        }
    }
    __syncthreads();

    const float mn1  = funkey(g_mn1[b]);
    const float inv1 = 1.0f / (funkey(g_mx1[b]) - mn1);

    const int ci   = 26 * w + lane + 1;           // f_s col of ct
    const int ocol = 26 * w + lane - 3;           // output column rel. t0
    const int gx   = t0 + ocol;                   // global time col of this lane
    const bool out_ok = (lane >= 3) && (lane <= 28) && (ocol < TT);

    float ring[5];
    float w0 = 0.f, w1 = 0.f, w2 = 0.f;
    float bmx = -INFINITY, bmn = INFINITY;

    float fa = f_s[0][ci];
    float tl = f_s[1][ci - 1], tc = f_s[1][ci], tr = f_s[1][ci + 1];

#pragma unroll
    for (int s = 0; s < 38; s++) {                // p1 row pr = s - 3 in [-3, 34]
        float nl = f_s[s + 2][ci - 1], nc = f_s[s + 2][ci], nr = f_s[s + 2][ci + 1];
        bool m = (tc >= fa) && (tc >= nc) && (tc >= tl) && (tc >= tr);
        ring[s % 5] = m ? (tc - mn1) * inv1 : 0.f;

        if (s >= 4) {
            const int r = s - 5;                  // blurred row in [-1, 32]
            float wnew;
            if ((topE && r == -1) || (botE && r == 32)) {
                wnew = -INFINITY;                 // SAME-pad for peak2 freq test
            } else {
                // freq blur from ring (p1 rows r-2..r+2)
                float p0  = ring[(s - 4) % 5];
                float p1v = ring[(s - 3) % 5];
                float p2  = ring[(s - 2) % 5];
                float p3  = ring[(s - 1) % 5];
                float p4  = ring[ s      % 5];
                float tv;
                if (topE && r == 0)
                    tv = fmaf(2.f * gw1, p3, fmaf(2.f * gw0, p4, gw2 * p2));
                else if (topE && r == 1)
                    tv = fmaf(gw1, p1v, fmaf(gw0 + gw2, p2, fmaf(gw1, p3, gw0 * p4)));
                else if (botE && r == 30)
                    tv = fmaf(gw0, p0, fmaf(gw1, p1v, fmaf(gw2 + gw0, p2, gw1 * p3)));
                else if (botE && r == 31)
                    tv = fmaf(2.f * gw0, p0, fmaf(2.f * gw1, p1v, gw2 * p2));
                else {
                    float s0 = p0 + p4, s1 = p1v + p3;
                    tv = fmaf(gw0, s0, fmaf(gw1, s1, gw2 * p2));
                }
                // time blur via shuffles
                float vm1 = __shfl_up_sync(0xffffffffu, tv, 1);
                float vm2 = __shfl_up_sync(0xffffffffu, tv, 2);
                float vp1 = __shfl_down_sync(0xffffffffu, tv, 1);
                float vp2 = __shfl_down_sync(0xffffffffu, tv, 2);
                if (gx == 0)
                    wnew = fmaf(2.f * gw1, vp1, fmaf(2.f * gw0, vp2, gw2 * tv));
                else if (gx == 1)
                    wnew = fmaf(gw1, vm1, fmaf(gw0 + gw2, tv, fmaf(gw1, vp1, gw0 * vp2)));
                else if (gx == T_ - 2)
                    wnew = fmaf(gw0, vm2, fmaf(gw1, vm1, fmaf(gw2 + gw0, tv, gw1 * vp1)));
                else if (gx == T_ - 1)
                    wnew = fmaf(2.f * gw0, vm2, fmaf(2.f * gw1, vm1, gw2 * tv));
                else {
                    float s0 = vm2 + vp2, s1 = vm1 + vp1;
                    wnew = fmaf(gw0, s0, fmaf(gw1, s1, gw2 * tv));
                }
            }
            w2 = wnew;

            if (s >= 6) {
                const int q = s - 6;              // peak2 row in [0, 31]
                // time neighbors of w1 (row q)
                float wl = __shfl_up_sync(0xffffffffu, w1, 1);
                float wr = __shfl_down_sync(0xffffffffu, w1, 1);
                float wl_e = (gx == 0)      ? -INFINITY : wl;
                float wr_e = (gx == T_ - 1) ? -INFINITY : wr;
                bool m2 = (w1 >= w0) && (w1 >= w2) && (w1 >= wl_e) && (w1 >= wr_e);
                bool pred = out_ok && m2 && (w1 > 0.f);
                if (out_ok) { bmx = fmaxf(bmx, w1); bmn = fminf(bmn, w1); }

                unsigned bal = __ballot_sync(0xffffffffu, pred);
                if (bal) {
                    unsigned base = 0;
                    if (lane == 0) base = atomicAdd(&s_cnt, (unsigned)__popc(bal));
                    base = __shfl_sync(0xffffffffu, base, 0);
                    if (pred) {
                        unsigned pos = base + (unsigned)__popc(bal & ((1u << lane) - 1u));
                        if (pos < SLCAP) {
                            s_list[pos].x = (unsigned)((fr0 + q) * T_ + gx);
                            s_list[pos].y = __float_as_uint(w1);
                        }
                    }
                }
            }
            w0 = w1; w1 = w2;
        }
        fa = tc; tl = nl; tc = nc; tr = nr;
    }

    // ---- per-batch min/max of the blurred field ----
#pragma unroll
    for (int o = 16; o > 0; o >>= 1) {
        bmx = fmaxf(bmx, __shfl_xor_sync(0xffffffffu, bmx, o));
        bmn = fminf(bmn, __shfl_xor_sync(0xffffffffu, bmn, o));
    }
    if (lane == 0) { smx[w] = bmx; smn[w] = bmn; }
    __syncthreads();
    if (tid == 0) {
        bmx = smx[0]; bmn = smn[0];
#pragma unroll
        for (int i = 1; i < 5; i++) {
            bmx = fmaxf(bmx, smx[i]); bmn = fminf(bmn, smn[i]);
        }
        atomicMax(&g_mx2[b], fkey(bmx));
        atomicMin(&g_mn2[b], fkey(bmn));
        unsigned cnt = s_cnt; if (cnt > SLCAP) cnt = SLCAP;
        s_cnt = cnt;
        s_gbase = atomicAdd(&g_ccnt[b], cnt);
    }
    __syncthreads();

    // ---- flush block candidate list to the per-batch global list ----
    unsigned cnt = s_cnt, gbase = s_gbase;
    uint2* gc = g_cand + (size_t)b * CAP;
    for (unsigned i = tid; i < cnt; i += NTHR) {
        unsigned p = gbase + i;
        if (p < CAP) gc[p] = s_list[i];
    }
}

// Stage C: per batch, select the first PADL (row-major) candidates with
// val > 0, in order, and write the [3, PADL] output. One block per batch.
__global__ __launch_bounds__(1024)
void final_k(float* __restrict__ out) {
    __shared__ int hist[256];
    __shared__ unsigned long long keys[512];
    __shared__ int s_par[4];   // R, C1, Cb, K
    __shared__ int s_cnt;

    const int b = blockIdx.x;
    const int tid = threadIdx.x;
    unsigned n = g_ccnt[b]; if (n > CAP) n = CAP;
    const float mn2 = funkey(g_mn2[b]);
    const float rng2 = funkey(g_mx2[b]) - mn2;
    const uint2* cand = g_cand + (size_t)b * CAP;
    float* ob = out + b * 3 * PADL;

    if (tid < 3 * PADL) ob[tid] = 0.f;
    if (tid < 256) hist[tid] = 0;
    if (tid == 0) s_cnt = 0;
    __syncthreads();

    // Pass 1: histogram of valid candidates by freq row.
    for (unsigned i = tid; i < n; i += 1024) {
        uint2 c = cand[i];
        if (__uint_as_float(c.y) > mn2) atomicAdd(&hist[c.x >> 12], 1);
    }
    __syncthreads();
    if (tid == 0) {
        int cum = 0, R = 256, C1 = 0;
        for (int r = 0; r < 256; r++) {
            int h = hist[r];
            if (R == 256 && cum + h >= PADL) { R = r; C1 = cum; }
            cum += h;
        }
        if (cum <= PADL) { R = 256; C1 = cum; }   // collect everything
        s_par[0] = R; s_par[1] = C1;
        s_par[3] = (cum < PADL) ? cum : PADL;
    }
    __syncthreads();
    const int R = s_par[0];
    const int K = s_par[3];
    int Cb = 256;

    if (R < 256) {
        // Pass 2: 16-col-bucket histogram within cutoff row R.
        if (tid < 256) hist[tid] = 0;
        __syncthreads();
        for (unsigned i = tid; i < n; i += 1024) {
            uint2 c = cand[i];
            if ((c.x >> 12) == (unsigned)R && __uint_as_float(c.y) > mn2)
                atomicAdd(&hist[(c.x & (T_ - 1)) >> 4], 1);
        }
        __syncthreads();
        if (tid == 0) {
            int cum = s_par[1], CbL = 255;
            for (int bb = 0; bb < 256; bb++) {
                cum += hist[bb];
                if (cum >= PADL) { CbL = bb; break; }
            }
            s_par[2] = CbL;
        }
        __syncthreads();
        Cb = s_par[2];
    }

    // Pass 3: collect candidates below the cutoff (<= 256 + 15 entries).
    for (unsigned i = tid; i < n; i += 1024) {
        uint2 c = cand[i];
        if (__uint_as_float(c.y) > mn2) {
            int row = c.x >> 12;
            bool keep = (row < R) ||
                        (row == R && (int)((c.x & (T_ - 1)) >> 4) <= Cb);
            if (keep) {
                int p = atomicAdd(&s_cnt, 1);
                if (p < 512)
                    keys[p] = ((unsigned long long)c.x << 32) | (unsigned long long)c.y;
            }
        }
    }
    __syncthreads();
    int cnt = s_cnt; if (cnt > 512) cnt = 512;
    for (int i = tid; i < 512; i += 1024)
        if (i >= cnt) keys[i] = 0xFFFFFFFFFFFFFFFFull;
    __syncthreads();

    // Bitonic sort 512 by packed (idx, vbits) key (idx unique).
    for (int k = 2; k <= 512; k <<= 1) {
        for (int j = k >> 1; j > 0; j >>= 1) {
            if (tid < 512) {
                int i2 = tid, ixj = i2 ^ j;
                if (ixj > i2) {
                    bool up = ((i2 & k) == 0);
                    unsigned long long a = keys[i2], c2 = keys[ixj];
                    if ((a > c2) == up) { keys[i2] = c2; keys[ixj] = a; }
                }
            }
            __syncthreads();
        }
    }

    if (tid < K) {
        unsigned long long e = keys[tid];
        unsigned idx = (unsigned)(e >> 32);
        float v = __uint_as_float((unsigned)(e & 0xFFFFFFFFull));
        ob[tid]            = (float)(idx >> 12) * (1.0f / F_);
        ob[PADL + tid]     = (float)(idx & (T_ - 1)) * (1.0f / T_);
        ob[2 * PADL + tid] = __fdiv_rn(v - mn2, rng2);
    }
}

extern "C" void kernel_launch(void* const* d_in, const int* in_sizes, int n_in,
                              void* d_out, int out_size) {
    const float* in = (const float*)d_in[0];
    float* out = (float*)d_out;

    // Gaussian weights, fp32, same formula as the reference.
    float g[5];
    float s = 0.f;
    for (int i = 0; i < 5; i++) {
        float c = (float)(i - 2);
        g[i] = expf(-0.5f * c * c);
    }
    for (int i = 0; i < 5; i++) s += g[i];
    for (int i = 0; i < 5; i++) g[i] = g[i] / s;

    init_k<<<1, 32>>>();
    minmax1_k<<<dim3(64, B_), 256>>>(in);
    blur_k<<<dim3(T_ / TT, F_ / TF, B_), NTHR>>>(in, g[0], g[1], g[2]);
    final_k<<<B_, 1024>>>(out);
}